// round 1
// baseline (speedup 1.0000x reference)
#include <cuda_runtime.h>
#include <math.h>

// ---------------------------------------------------------------------------
// Problem constants
// ---------------------------------------------------------------------------
#define BSZ   64      // batch
#define IMG   128
#define CIN0  3
#define CH    24      // conv channels
#define QD    11
#define AD    10
#define NN    64      // objects per image (8x8)
#define FD    26      // CH + 2 coords
#define HID   256
#define EPSV  1e-5f

// ---------------------------------------------------------------------------
// Scratch (device globals; no allocations allowed)
// ---------------------------------------------------------------------------
__device__ float  g_x1[BSZ*CH*64*64];   // 6.29M
__device__ float  g_x2[BSZ*CH*32*32];
__device__ float  g_x3[BSZ*CH*16*16];
__device__ float  g_x4[BSZ*CH*8*8];
__device__ float  g_u [BSZ*NN*HID];
__device__ float  g_v [BSZ*NN*HID];
__device__ float  g_s [BSZ*HID];
__device__ float  g_gsum[BSZ*HID];
__device__ double g_bnsum[4*CH];
__device__ double g_bnsq [4*CH];
__device__ float  g_scale[CH];
__device__ float  g_shift[CH];

// ---------------------------------------------------------------------------
// Zero the accumulators (graph replays require re-zeroing every launch)
// ---------------------------------------------------------------------------
__global__ void zero_kernel(float* gsum, double* bnsum, double* bnsq) {
    int idx = blockIdx.x * blockDim.x + threadIdx.x;
    if (idx < BSZ*HID) gsum[idx] = 0.f;
    if (idx < 4*CH) { bnsum[idx] = 0.0; bnsq[idx] = 0.0; }
}

// ---------------------------------------------------------------------------
// Conv (k=3, stride=2, pad=1) + bias + ReLU
// ---------------------------------------------------------------------------
template<int CI, int CO, int HIN, int HOUT>
__global__ void conv_relu_kernel(const float* __restrict__ in,
                                 const float* __restrict__ w,
                                 const float* __restrict__ bias,
                                 float* __restrict__ out) {
    __shared__ float ws[CI*CO*9];
    __shared__ float bs[CO];
    for (int i = threadIdx.x; i < CI*CO*9; i += blockDim.x) ws[i] = w[i];
    if (threadIdx.x < CO) bs[threadIdx.x] = bias[threadIdx.x];
    __syncthreads();

    int idx = blockIdx.x * blockDim.x + threadIdx.x;
    const int T = BSZ * CO * HOUT * HOUT;
    if (idx >= T) return;
    int ox = idx % HOUT;
    int oy = (idx / HOUT) % HOUT;
    int co = (idx / (HOUT*HOUT)) % CO;
    int b  = idx / (HOUT*HOUT*CO);

    float acc = bs[co];
    int iy0 = oy*2 - 1, ix0 = ox*2 - 1;
    for (int ci = 0; ci < CI; ci++) {
        const float* ip = in + ((b*CI + ci) * HIN) * HIN;
        const float* wp = ws + (co*CI + ci) * 9;
        #pragma unroll
        for (int ky = 0; ky < 3; ky++) {
            int iy = iy0 + ky;
            if (iy < 0 || iy >= HIN) continue;
            #pragma unroll
            for (int kx = 0; kx < 3; kx++) {
                int ix = ix0 + kx;
                if (ix < 0 || ix >= HIN) continue;
                acc += ip[iy*HIN + ix] * wp[ky*3 + kx];
            }
        }
    }
    out[idx] = fmaxf(acc, 0.f);
}

// ---------------------------------------------------------------------------
// BatchNorm (train-mode batch stats): stats -> finalize -> apply
// ---------------------------------------------------------------------------
__global__ void bn_stats_kernel(const float* __restrict__ x,
                                double* __restrict__ sum, double* __restrict__ sq,
                                int HW) {
    int c = blockIdx.x;
    int total = BSZ * HW;
    double s = 0.0, s2 = 0.0;
    for (int idx = blockIdx.y*blockDim.x + threadIdx.x; idx < total;
         idx += gridDim.y*blockDim.x) {
        int b  = idx / HW;
        int hw = idx - b*HW;
        float v = x[(size_t)(b*CH + c)*HW + hw];
        s  += v;
        s2 += (double)v * v;
    }
    __shared__ double ssum[256], ssq[256];
    ssum[threadIdx.x] = s; ssq[threadIdx.x] = s2;
    __syncthreads();
    for (int off = 128; off > 0; off >>= 1) {
        if (threadIdx.x < off) {
            ssum[threadIdx.x] += ssum[threadIdx.x+off];
            ssq [threadIdx.x] += ssq [threadIdx.x+off];
        }
        __syncthreads();
    }
    if (threadIdx.x == 0) {
        atomicAdd(&sum[c], ssum[0]);
        atomicAdd(&sq [c], ssq [0]);
    }
}

__global__ void bn_finalize_kernel(const double* __restrict__ sum,
                                   const double* __restrict__ sq,
                                   const float* __restrict__ bg,
                                   const float* __restrict__ bb,
                                   float* __restrict__ scale,
                                   float* __restrict__ shift,
                                   int HW) {
    int c = threadIdx.x;
    if (c >= CH) return;
    double cnt = (double)BSZ * HW;
    double m   = sum[c] / cnt;
    double var = sq[c] / cnt - m * m;
    float inv  = rsqrtf((float)var + EPSV);
    float sc   = bg[c] * inv;
    scale[c] = sc;
    shift[c] = bb[c] - (float)m * sc;
}

__global__ void bn_apply_kernel(float* __restrict__ x,
                                const float* __restrict__ scale,
                                const float* __restrict__ shift,
                                int HW, int total) {
    int idx = blockIdx.x * blockDim.x + threadIdx.x;
    if (idx >= total) return;
    int c = (idx / HW) % CH;
    x[idx] = x[idx] * scale[c] + shift[c];
}

// ---------------------------------------------------------------------------
// Layer-1 factorization: u = o @ gw1[0:26], v = o @ gw1[26:52]
// ---------------------------------------------------------------------------
__global__ void uv_kernel(const float* __restrict__ x4,
                          const float* __restrict__ gw1,
                          float* __restrict__ u, float* __restrict__ v) {
    __shared__ float o[FD];
    int bn = blockIdx.x;           // b*64 + n
    int b = bn >> 6, n = bn & 63;
    int tid = threadIdx.x;
    if (tid < CH)       o[tid] = x4[(b*CH + tid)*64 + n];
    else if (tid == CH)     o[CH]   = (float)(n >> 3) * 0.125f;
    else if (tid == CH + 1) o[CH+1] = (float)(n & 7)  * 0.125f;
    __syncthreads();
    float us = 0.f, vs = 0.f;
    #pragma unroll
    for (int f = 0; f < FD; f++) {
        float ov = o[f];
        us += ov * gw1[f*HID + tid];
        vs += ov * gw1[(FD + f)*HID + tid];
    }
    u[bn*HID + tid] = us;
    v[bn*HID + tid] = vs;
}

// s = q @ gw1[52:63] + gb1
__global__ void s_kernel(const float* __restrict__ q,
                         const float* __restrict__ gw1,
                         const float* __restrict__ gb1,
                         float* __restrict__ s) {
    __shared__ float qv[QD];
    int b = blockIdx.x, tid = threadIdx.x;
    if (tid < QD) qv[tid] = q[b*QD + tid];
    __syncthreads();
    float acc = gb1[tid];
    #pragma unroll
    for (int t = 0; t < QD; t++)
        acc += qv[t] * gw1[(2*FD + t)*HID + tid];
    s[b*HID + tid] = acc;
}

// ---------------------------------------------------------------------------
// Fused relational core: per block = one (b, i) -> 64 pairs (all j)
//   h1 = relu(u_i + v_j + s_b)     [SMEM]
//   h  = relu(h @ W + b)  x3       [SMEM ping-pong, 8x8 register tiles]
//   gsum[b] += sum_j h4            [atomic]
// ---------------------------------------------------------------------------
__device__ __forceinline__ void gemm_relu(const float* __restrict__ hin,
                                          float* __restrict__ hout,
                                          float* __restrict__ Wt,
                                          const float* __restrict__ W,
                                          const float* __restrict__ bias,
                                          int tid) {
    const int rg = tid >> 5, cg = tid & 31;
    const int r0 = rg * 8, c0 = cg * 8;
    float acc[8][8];
    #pragma unroll
    for (int ci = 0; ci < 8; ci++) {
        float bv = bias[c0 + ci];
        #pragma unroll
        for (int ri = 0; ri < 8; ri++) acc[ri][ci] = bv;
    }
    for (int kb = 0; kb < HID; kb += 32) {
        // stage 32x256 weight slab into SMEM (coalesced float4)
        const float4* Wg = (const float4*)(W + kb * HID);
        float4* Ws = (float4*)Wt;
        #pragma unroll
        for (int q = 0; q < 8; q++)
            Ws[q*256 + tid] = Wg[q*256 + tid];
        __syncthreads();
        #pragma unroll
        for (int k = 0; k < 32; k++) {
            float a[8];
            #pragma unroll
            for (int ri = 0; ri < 8; ri++)
                a[ri] = hin[(r0+ri)*HID + kb + k];   // warp-broadcast LDS
            float4 b0 = *(const float4*)&Wt[k*HID + c0];
            float4 b1 = *(const float4*)&Wt[k*HID + c0 + 4];
            float bv[8] = {b0.x,b0.y,b0.z,b0.w,b1.x,b1.y,b1.z,b1.w};
            #pragma unroll
            for (int ri = 0; ri < 8; ri++)
                #pragma unroll
                for (int ci = 0; ci < 8; ci++)
                    acc[ri][ci] += a[ri] * bv[ci];
        }
        __syncthreads();
    }
    #pragma unroll
    for (int ri = 0; ri < 8; ri++)
        #pragma unroll
        for (int ci = 0; ci < 8; ci++)
            hout[(r0+ri)*HID + c0 + ci] = fmaxf(acc[ri][ci], 0.f);
}

__global__ void __launch_bounds__(256, 1)
rn_main_kernel(const float* __restrict__ u, const float* __restrict__ v,
               const float* __restrict__ s, float* __restrict__ gsum,
               const float* __restrict__ gw2, const float* __restrict__ gb2,
               const float* __restrict__ gw3, const float* __restrict__ gb3,
               const float* __restrict__ gw4, const float* __restrict__ gb4) {
    extern __shared__ float sm[];
    float* hA = sm;                    // 64x256
    float* hB = sm + 64*HID;           // 64x256
    float* Wt = sm + 2*64*HID;         // 32x256

    int tid = threadIdx.x;
    int b = blockIdx.x >> 6;
    int i = blockIdx.x & 63;

    // h1[j][c] = relu(u[b,i,c] + v[b,j,c] + s[b,c])
    float uval = u[(b*NN + i)*HID + tid] + s[b*HID + tid];
    const float* vp = v + (size_t)b*NN*HID + tid;
    #pragma unroll 4
    for (int r = 0; r < NN; r++)
        hA[r*HID + tid] = fmaxf(uval + vp[r*HID], 0.f);
    __syncthreads();

    gemm_relu(hA, hB, Wt, gw2, gb2, tid);
    gemm_relu(hB, hA, Wt, gw3, gb3, tid);
    gemm_relu(hA, hB, Wt, gw4, gb4, tid);
    __syncthreads();

    float acc = 0.f;
    #pragma unroll 8
    for (int r = 0; r < NN; r++) acc += hB[r*HID + tid];
    atomicAdd(&gsum[b*HID + tid], acc);
}

// ---------------------------------------------------------------------------
// f_phi: mean -> 256 -> 256 -> 10
// ---------------------------------------------------------------------------
__global__ void fphi_kernel(const float* __restrict__ gsum,
                            const float* __restrict__ fw1, const float* __restrict__ fb1,
                            const float* __restrict__ fw2, const float* __restrict__ fb2,
                            const float* __restrict__ fw3, const float* __restrict__ fb3,
                            float* __restrict__ out) {
    __shared__ float ga[HID], gb[HID];
    int b = blockIdx.x, tid = threadIdx.x;
    ga[tid] = gsum[b*HID + tid] * (1.0f / (NN*NN));
    __syncthreads();
    float acc = fb1[tid];
    for (int f = 0; f < HID; f++) acc += ga[f] * fw1[f*HID + tid];
    gb[tid] = fmaxf(acc, 0.f);
    __syncthreads();
    acc = fb2[tid];
    for (int f = 0; f < HID; f++) acc += gb[f] * fw2[f*HID + tid];
    ga[tid] = fmaxf(acc, 0.f);
    __syncthreads();
    if (tid < AD) {
        float o = fb3[tid];
        for (int f = 0; f < HID; f++) o += ga[f] * fw3[f*AD + tid];
        out[b*AD + tid] = o;
    }
}

// ---------------------------------------------------------------------------
// Launch
// ---------------------------------------------------------------------------
extern "C" void kernel_launch(void* const* d_in, const int* in_sizes, int n_in,
                              void* d_out, int out_size) {
    (void)in_sizes; (void)n_in; (void)out_size;
    const float* img = (const float*)d_in[0];
    const float* q   = (const float*)d_in[1];
    const float* cw[4] = {(const float*)d_in[2],  (const float*)d_in[6],
                          (const float*)d_in[10], (const float*)d_in[14]};
    const float* cb[4] = {(const float*)d_in[3],  (const float*)d_in[7],
                          (const float*)d_in[11], (const float*)d_in[15]};
    const float* bg[4] = {(const float*)d_in[4],  (const float*)d_in[8],
                          (const float*)d_in[12], (const float*)d_in[16]};
    const float* bb[4] = {(const float*)d_in[5],  (const float*)d_in[9],
                          (const float*)d_in[13], (const float*)d_in[17]};
    const float* gw1 = (const float*)d_in[18]; const float* gb1 = (const float*)d_in[19];
    const float* gw2 = (const float*)d_in[20]; const float* gb2 = (const float*)d_in[21];
    const float* gw3 = (const float*)d_in[22]; const float* gb3 = (const float*)d_in[23];
    const float* gw4 = (const float*)d_in[24]; const float* gb4 = (const float*)d_in[25];
    const float* fw1 = (const float*)d_in[26]; const float* fb1 = (const float*)d_in[27];
    const float* fw2 = (const float*)d_in[28]; const float* fb2 = (const float*)d_in[29];
    const float* fw3 = (const float*)d_in[30]; const float* fb3 = (const float*)d_in[31];
    float* out = (float*)d_out;

    float  *x1, *x2, *x3, *x4, *u, *v, *s, *gsum, *scale, *shift;
    double *bnsum, *bnsq;
    cudaGetSymbolAddress((void**)&x1,    g_x1);
    cudaGetSymbolAddress((void**)&x2,    g_x2);
    cudaGetSymbolAddress((void**)&x3,    g_x3);
    cudaGetSymbolAddress((void**)&x4,    g_x4);
    cudaGetSymbolAddress((void**)&u,     g_u);
    cudaGetSymbolAddress((void**)&v,     g_v);
    cudaGetSymbolAddress((void**)&s,     g_s);
    cudaGetSymbolAddress((void**)&gsum,  g_gsum);
    cudaGetSymbolAddress((void**)&scale, g_scale);
    cudaGetSymbolAddress((void**)&shift, g_shift);
    cudaGetSymbolAddress((void**)&bnsum, g_bnsum);
    cudaGetSymbolAddress((void**)&bnsq,  g_bnsq);

    cudaFuncSetAttribute(rn_main_kernel,
                         cudaFuncAttributeMaxDynamicSharedMemorySize, 163840);

    zero_kernel<<<64, 256>>>(gsum, bnsum, bnsq);

    // conv block 1: 128 -> 64
    conv_relu_kernel<3,24,128,64><<<(BSZ*CH*64*64+255)/256, 256>>>(img, cw[0], cb[0], x1);
    bn_stats_kernel<<<dim3(CH,16), 256>>>(x1, bnsum+0, bnsq+0, 64*64);
    bn_finalize_kernel<<<1, 32>>>(bnsum+0, bnsq+0, bg[0], bb[0], scale, shift, 64*64);
    bn_apply_kernel<<<(BSZ*CH*64*64+255)/256, 256>>>(x1, scale, shift, 64*64, BSZ*CH*64*64);

    // conv block 2: 64 -> 32
    conv_relu_kernel<24,24,64,32><<<(BSZ*CH*32*32+255)/256, 256>>>(x1, cw[1], cb[1], x2);
    bn_stats_kernel<<<dim3(CH,8), 256>>>(x2, bnsum+CH, bnsq+CH, 32*32);
    bn_finalize_kernel<<<1, 32>>>(bnsum+CH, bnsq+CH, bg[1], bb[1], scale, shift, 32*32);
    bn_apply_kernel<<<(BSZ*CH*32*32+255)/256, 256>>>(x2, scale, shift, 32*32, BSZ*CH*32*32);

    // conv block 3: 32 -> 16
    conv_relu_kernel<24,24,32,16><<<(BSZ*CH*16*16+255)/256, 256>>>(x2, cw[2], cb[2], x3);
    bn_stats_kernel<<<dim3(CH,4), 256>>>(x3, bnsum+2*CH, bnsq+2*CH, 16*16);
    bn_finalize_kernel<<<1, 32>>>(bnsum+2*CH, bnsq+2*CH, bg[2], bb[2], scale, shift, 16*16);
    bn_apply_kernel<<<(BSZ*CH*16*16+255)/256, 256>>>(x3, scale, shift, 16*16, BSZ*CH*16*16);

    // conv block 4: 16 -> 8
    conv_relu_kernel<24,24,16,8><<<(BSZ*CH*8*8+255)/256, 256>>>(x3, cw[3], cb[3], x4);
    bn_stats_kernel<<<dim3(CH,2), 256>>>(x4, bnsum+3*CH, bnsq+3*CH, 8*8);
    bn_finalize_kernel<<<1, 32>>>(bnsum+3*CH, bnsq+3*CH, bg[3], bb[3], scale, shift, 8*8);
    bn_apply_kernel<<<(BSZ*CH*8*8+255)/256, 256>>>(x4, scale, shift, 8*8, BSZ*CH*8*8);

    // g_theta layer-1 factorization
    uv_kernel<<<BSZ*NN, 256>>>(x4, gw1, u, v);
    s_kernel<<<BSZ, 256>>>(q, gw1, gb1, s);

    // fused relational core (103 GFLOP)
    rn_main_kernel<<<BSZ*NN, 256, 163840>>>(u, v, s, gsum,
                                            gw2, gb2, gw3, gb3, gw4, gb4);

    // f_phi
    fphi_kernel<<<BSZ, 256>>>(gsum, fw1, fb1, fw2, fb2, fw3, fb3, out);
}

// round 3
// speedup vs baseline: 2.4816x; 2.4816x over previous
#include <cuda_runtime.h>
#include <math.h>
#include <stdint.h>

// ---------------------------------------------------------------------------
// Problem constants
// ---------------------------------------------------------------------------
#define BSZ   64
#define IMG   128
#define CH    24
#define QD    11
#define AD    10
#define NN    64      // objects per image (8x8)
#define FD    26      // CH + 2 coords
#define HID   256
#define EPSV  1e-5f

// rn_mma geometry
#define M_CTA     128            // pair rows per CTA (2 i-values x 64 j)
#define HA_STRIDE 268            // padded fp32 stride (conflict-free A frags, 16B aligned)
#define WSLAB_B   32768          // 4 k-steps of fragment-ordered weights
#define DYN_RN    (2*WSLAB_B + M_CTA*HA_STRIDE*4)   // 65536 + 137216 = 202752

// ---------------------------------------------------------------------------
// Scratch
// ---------------------------------------------------------------------------
__device__ float  g_x1[BSZ*CH*64*64];
__device__ float  g_x2[BSZ*CH*32*32];
__device__ float  g_x3[BSZ*CH*16*16];
__device__ float  g_x4[BSZ*CH*8*8];
__device__ float  g_u [BSZ*NN*HID];
__device__ float  g_v [BSZ*NN*HID];
__device__ float  g_s [BSZ*HID];
__device__ float  g_gsum[BSZ*HID];
__device__ uint32_t g_wf[3*HID*HID];   // fragment-ordered tf32 weights (uint2 pairs)
__device__ double g_bnsum[4*CH];
__device__ double g_bnsq [4*CH];
__device__ float  g_scale[CH];
__device__ float  g_shift[CH];

// ---------------------------------------------------------------------------
// Helpers
// ---------------------------------------------------------------------------
__device__ __forceinline__ uint32_t smem_u32(const void* p) {
    uint32_t a;
    asm("{ .reg .u64 t; cvta.to.shared.u64 t, %1; cvt.u32.u64 %0, t; }"
        : "=r"(a) : "l"(p));
    return a;
}
__device__ __forceinline__ uint32_t f2tf32(float f) {
    uint32_t u; asm("cvt.rna.tf32.f32 %0, %1;" : "=r"(u) : "f"(f)); return u;
}
__device__ __forceinline__ void mma_tf32(float* c, const uint32_t* a,
                                         uint32_t b0, uint32_t b1) {
    asm volatile(
        "mma.sync.aligned.m16n8k8.row.col.f32.tf32.tf32.f32 "
        "{%0,%1,%2,%3}, {%4,%5,%6,%7}, {%8,%9}, {%0,%1,%2,%3};"
        : "+f"(c[0]), "+f"(c[1]), "+f"(c[2]), "+f"(c[3])
        : "r"(a[0]), "r"(a[1]), "r"(a[2]), "r"(a[3]), "r"(b0), "r"(b1));
}
__device__ __forceinline__ void cp16(uint32_t dst, const void* src) {
    asm volatile("cp.async.cg.shared.global [%0], [%1], 16;"
                 :: "r"(dst), "l"(__cvta_generic_to_global(src)) : "memory");
}
#define CP_COMMIT() asm volatile("cp.async.commit_group;" ::: "memory")
#define CP_WAIT1()  asm volatile("cp.async.wait_group 1;" ::: "memory")
#define CP_WAIT0()  asm volatile("cp.async.wait_group 0;" ::: "memory")

// ---------------------------------------------------------------------------
__global__ void zero_kernel(float* gsum, double* bnsum, double* bnsq) {
    int idx = blockIdx.x * blockDim.x + threadIdx.x;
    if (idx < BSZ*HID) gsum[idx] = 0.f;
    if (idx < 4*CH) { bnsum[idx] = 0.0; bnsq[idx] = 0.0; }
}

// Fragment-ordered tf32 weights:
// wf[((l*32 + k)*32 + j)*32 + lane] = uint2{ tf32(gw_l[(8k+lane%4)*256 + 8j+lane/4]),
//                                            tf32(gw_l[(8k+lane%4+4)*256 + 8j+lane/4]) }
__global__ void wfrag_kernel(const float* __restrict__ gw2,
                             const float* __restrict__ gw3,
                             const float* __restrict__ gw4,
                             uint32_t* __restrict__ wf) {
    int idx = blockIdx.x * blockDim.x + threadIdx.x;   // [0, 3*32768)
    if (idx >= 3*32768) return;
    int l = idx >> 15;
    int r = idx & 32767;
    int k = r >> 10;
    int j = (r >> 5) & 31;
    int t = r & 31;
    const float* g = (l == 0) ? gw2 : (l == 1) ? gw3 : gw4;
    int n = 8*j + (t >> 2);
    int k0 = 8*k + (t & 3);
    uint2 val;
    val.x = f2tf32(g[(size_t)k0*HID + n]);
    val.y = f2tf32(g[(size_t)(k0+4)*HID + n]);
    ((uint2*)wf)[idx] = val;
}

// ---------------------------------------------------------------------------
// Conv (k=3, stride=2, pad=1) + bias + ReLU
// ---------------------------------------------------------------------------
template<int CI, int CO, int HIN, int HOUT>
__global__ void conv_relu_kernel(const float* __restrict__ in,
                                 const float* __restrict__ w,
                                 const float* __restrict__ bias,
                                 float* __restrict__ out) {
    __shared__ float ws[CI*CO*9];
    __shared__ float bs[CO];
    for (int i = threadIdx.x; i < CI*CO*9; i += blockDim.x) ws[i] = w[i];
    if (threadIdx.x < CO) bs[threadIdx.x] = bias[threadIdx.x];
    __syncthreads();

    int idx = blockIdx.x * blockDim.x + threadIdx.x;
    const int T = BSZ * CO * HOUT * HOUT;
    if (idx >= T) return;
    int ox = idx % HOUT;
    int oy = (idx / HOUT) % HOUT;
    int co = (idx / (HOUT*HOUT)) % CO;
    int b  = idx / (HOUT*HOUT*CO);

    float acc = bs[co];
    int iy0 = oy*2 - 1, ix0 = ox*2 - 1;
    for (int ci = 0; ci < CI; ci++) {
        const float* ip = in + ((b*CI + ci) * HIN) * HIN;
        const float* wp = ws + (co*CI + ci) * 9;
        #pragma unroll
        for (int ky = 0; ky < 3; ky++) {
            int iy = iy0 + ky;
            if (iy < 0 || iy >= HIN) continue;
            #pragma unroll
            for (int kx = 0; kx < 3; kx++) {
                int ix = ix0 + kx;
                if (ix < 0 || ix >= HIN) continue;
                acc += ip[iy*HIN + ix] * wp[ky*3 + kx];
            }
        }
    }
    out[idx] = fmaxf(acc, 0.f);
}

// ---------------------------------------------------------------------------
// BatchNorm pieces
// ---------------------------------------------------------------------------
__global__ void bn_stats_kernel(const float* __restrict__ x,
                                double* __restrict__ sum, double* __restrict__ sq,
                                int HW) {
    int c = blockIdx.x;
    int total = BSZ * HW;
    double s = 0.0, s2 = 0.0;
    for (int idx = blockIdx.y*blockDim.x + threadIdx.x; idx < total;
         idx += gridDim.y*blockDim.x) {
        int b  = idx / HW;
        int hw = idx - b*HW;
        float v = x[(size_t)(b*CH + c)*HW + hw];
        s  += v;
        s2 += (double)v * v;
    }
    __shared__ double ssum[256], ssq[256];
    ssum[threadIdx.x] = s; ssq[threadIdx.x] = s2;
    __syncthreads();
    for (int off = 128; off > 0; off >>= 1) {
        if (threadIdx.x < off) {
            ssum[threadIdx.x] += ssum[threadIdx.x+off];
            ssq [threadIdx.x] += ssq [threadIdx.x+off];
        }
        __syncthreads();
    }
    if (threadIdx.x == 0) {
        atomicAdd(&sum[c], ssum[0]);
        atomicAdd(&sq [c], ssq [0]);
    }
}

__global__ void bn_finalize_kernel(const double* __restrict__ sum,
                                   const double* __restrict__ sq,
                                   const float* __restrict__ bg,
                                   const float* __restrict__ bb,
                                   float* __restrict__ scale,
                                   float* __restrict__ shift,
                                   int HW) {
    int c = threadIdx.x;
    if (c >= CH) return;
    double cnt = (double)BSZ * HW;
    double m   = sum[c] / cnt;
    double var = sq[c] / cnt - m * m;
    float inv  = rsqrtf((float)var + EPSV);
    float sc   = bg[c] * inv;
    scale[c] = sc;
    shift[c] = bb[c] - (float)m * sc;
}

__global__ void bn_apply_kernel(float* __restrict__ x,
                                const float* __restrict__ scale,
                                const float* __restrict__ shift,
                                int HW, int total) {
    int idx = blockIdx.x * blockDim.x + threadIdx.x;
    if (idx >= total) return;
    int c = (idx / HW) % CH;
    x[idx] = x[idx] * scale[c] + shift[c];
}

// ---------------------------------------------------------------------------
// Layer-1 factorization
// ---------------------------------------------------------------------------
__global__ void uv_kernel(const float* __restrict__ x4,
                          const float* __restrict__ gw1,
                          float* __restrict__ u, float* __restrict__ v) {
    __shared__ float o[FD];
    int bn = blockIdx.x;
    int b = bn >> 6, n = bn & 63;
    int tid = threadIdx.x;
    if (tid < CH)       o[tid] = x4[(b*CH + tid)*64 + n];
    else if (tid == CH)     o[CH]   = (float)(n >> 3) * 0.125f;
    else if (tid == CH + 1) o[CH+1] = (float)(n & 7)  * 0.125f;
    __syncthreads();
    float us = 0.f, vs = 0.f;
    #pragma unroll
    for (int f = 0; f < FD; f++) {
        float ov = o[f];
        us += ov * gw1[f*HID + tid];
        vs += ov * gw1[(FD + f)*HID + tid];
    }
    u[bn*HID + tid] = us;
    v[bn*HID + tid] = vs;
}

__global__ void s_kernel(const float* __restrict__ q,
                         const float* __restrict__ gw1,
                         const float* __restrict__ gb1,
                         float* __restrict__ s) {
    __shared__ float qv[QD];
    int b = blockIdx.x, tid = threadIdx.x;
    if (tid < QD) qv[tid] = q[b*QD + tid];
    __syncthreads();
    float acc = gb1[tid];
    #pragma unroll
    for (int t = 0; t < QD; t++)
        acc += qv[t] * gw1[(2*FD + t)*HID + tid];
    s[b*HID + tid] = acc;
}

// ---------------------------------------------------------------------------
// Tensor-core relational core (mma.sync tf32, baseline-PTX compatible).
// CTA: 512 thr (16 warps = 4 Mgroups x 4 Ngroups), M=128 rows, N=256, K=256, x3.
// hA: in-place SMEM activations (fp32 bits = tf32-rounded), stride 268.
// Weights: fragment-ordered, cp.async double-buffered 4-kstep slabs.
// ---------------------------------------------------------------------------
__global__ void __launch_bounds__(512, 1)
rn_mma_kernel(const float* __restrict__ u, const float* __restrict__ v,
              const float* __restrict__ sb, float* __restrict__ gsum,
              const uint32_t* __restrict__ wf,
              const float* __restrict__ gb2, const float* __restrict__ gb3,
              const float* __restrict__ gb4) {
    extern __shared__ char dyn[];
    uint32_t* hAu = (uint32_t*)(dyn + 2*WSLAB_B);
    const uint2* wbuf2 = (const uint2*)dyn;
    const uint32_t wsm = smem_u32(dyn);
    __shared__ float biasS[3*HID];
    __shared__ float colsum[HID];

    const int tid  = threadIdx.x;
    const int lane = tid & 31;
    const int warp = tid >> 5;
    const int mg   = warp & 3;    // row group: rows [mg*32, mg*32+32)
    const int ng   = warp >> 2;   // col group: cols [ng*64, ng*64+64)

    for (int i = tid; i < HID; i += 512) {
        biasS[i]         = gb2[i];
        biasS[HID + i]   = gb3[i];
        biasS[2*HID + i] = gb4[i];
    }
    if (tid < HID) colsum[tid] = 0.f;

    // ---- build h1 (tf32-rounded) in hA ----
    const int b  = blockIdx.x >> 5;
    const int i0 = (blockIdx.x & 31) * 2;
    {
        const int row = tid >> 2;
        const int c0  = (tid & 3) * 64;
        const int ii  = i0 + (row >> 6);
        const int jj  = row & 63;
        const float* up = u  + (size_t)(b*NN + ii) * HID;
        const float* vp = v  + (size_t)(b*NN + jj) * HID;
        const float* sp = sb + (size_t)b * HID;
        #pragma unroll
        for (int f = 0; f < 16; f++) {
            int c = c0 + f*4;
            float4 uu = *(const float4*)(up + c);
            float4 vv = *(const float4*)(vp + c);
            float4 ss = *(const float4*)(sp + c);
            uint4 hq;
            hq.x = f2tf32(fmaxf(uu.x + vv.x + ss.x, 0.f));
            hq.y = f2tf32(fmaxf(uu.y + vv.y + ss.y, 0.f));
            hq.z = f2tf32(fmaxf(uu.z + vv.z + ss.z, 0.f));
            hq.w = f2tf32(fmaxf(uu.w + vv.w + ss.w, 0.f));
            *(uint4*)(hAu + row*HA_STRIDE + c) = hq;
        }
    }

    // ---- prefetch W slab 0 ----
    {
        const char* src = (const char*)wf;
        #pragma unroll
        for (int i = 0; i < 4; i++)
            cp16(wsm + (i*512 + tid)*16, src + (i*512 + tid)*16);
        CP_COMMIT();
    }

    float acc[2][8][4];

    #pragma unroll 1
    for (int sl = 0; sl < 24; sl++) {
        const int l   = sl >> 3;
        const int cur = sl & 1;
        __syncthreads();                       // prev compute done -> safe to refill buf
        if (sl + 1 < 24) {
            const char* src = (const char*)wf + (size_t)(sl + 1) * WSLAB_B;
            uint32_t dst = wsm + (cur ^ 1) * WSLAB_B;
            #pragma unroll
            for (int i = 0; i < 4; i++)
                cp16(dst + (i*512 + tid)*16, src + (i*512 + tid)*16);
            CP_COMMIT();
            CP_WAIT1();
        } else {
            CP_WAIT0();
        }
        __syncthreads();                       // slab sl visible to all

        if ((sl & 7) == 0) {
            #pragma unroll
            for (int mt = 0; mt < 2; mt++)
                #pragma unroll
                for (int j = 0; j < 8; j++)
                    #pragma unroll
                    for (int c = 0; c < 4; c++)
                        acc[mt][j][c] = 0.f;
        }

        // compute 4 k-steps of this slab
        const uint2* wslab = wbuf2 + cur * (WSLAB_B/8);
        const int kbase = (sl & 7) * 4;
        #pragma unroll
        for (int kk = 0; kk < 4; kk++) {
            const int kcol = (kbase + kk) * 8;
            uint32_t a[2][4];
            #pragma unroll
            for (int mt = 0; mt < 2; mt++) {
                int rA = mg*32 + mt*16 + (lane >> 2);
                int cA = kcol + (lane & 3);
                a[mt][0] = hAu[rA*HA_STRIDE + cA];
                a[mt][1] = hAu[(rA+8)*HA_STRIDE + cA];
                a[mt][2] = hAu[rA*HA_STRIDE + cA + 4];
                a[mt][3] = hAu[(rA+8)*HA_STRIDE + cA + 4];
            }
            #pragma unroll
            for (int j = 0; j < 8; j++) {
                uint2 bb = wslab[(kk*32 + (ng*8 + j))*32 + lane];
                mma_tf32(acc[0][j], a[0], bb.x, bb.y);
                mma_tf32(acc[1][j], a[1], bb.x, bb.y);
            }
        }

        if ((sl & 7) == 7) {
            __syncthreads();                   // all K-loops done before hA overwrite
            if (l < 2) {
                const float* bl = biasS + l*HID;
                #pragma unroll
                for (int mt = 0; mt < 2; mt++) {
                    int rA = mg*32 + mt*16 + (lane >> 2);
                    #pragma unroll
                    for (int j = 0; j < 8; j++) {
                        int col = ng*64 + j*8 + 2*(lane & 3);
                        float b0 = bl[col], b1 = bl[col+1];
                        uint2 lo, hi;
                        lo.x = f2tf32(fmaxf(acc[mt][j][0] + b0, 0.f));
                        lo.y = f2tf32(fmaxf(acc[mt][j][1] + b1, 0.f));
                        hi.x = f2tf32(fmaxf(acc[mt][j][2] + b0, 0.f));
                        hi.y = f2tf32(fmaxf(acc[mt][j][3] + b1, 0.f));
                        *(uint2*)(hAu + rA*HA_STRIDE + col)     = lo;
                        *(uint2*)(hAu + (rA+8)*HA_STRIDE + col) = hi;
                    }
                }
                __syncthreads();
            } else {
                // final layer: relu(acc+bias), reduce over rows, SMEM colsum
                const float* bl = biasS + 2*HID;
                #pragma unroll
                for (int j = 0; j < 8; j++) {
                    int col = ng*64 + j*8 + 2*(lane & 3);
                    float b0 = bl[col], b1 = bl[col+1];
                    float s0 = 0.f, s1 = 0.f;
                    #pragma unroll
                    for (int mt = 0; mt < 2; mt++) {
                        s0 += fmaxf(acc[mt][j][0] + b0, 0.f)
                            + fmaxf(acc[mt][j][2] + b0, 0.f);
                        s1 += fmaxf(acc[mt][j][1] + b1, 0.f)
                            + fmaxf(acc[mt][j][3] + b1, 0.f);
                    }
                    #pragma unroll
                    for (int off = 4; off < 32; off <<= 1) {
                        s0 += __shfl_xor_sync(0xFFFFFFFFu, s0, off);
                        s1 += __shfl_xor_sync(0xFFFFFFFFu, s1, off);
                    }
                    if (lane < 4) {
                        atomicAdd(&colsum[col],     s0);
                        atomicAdd(&colsum[col + 1], s1);
                    }
                }
            }
        }
    }

    __syncthreads();
    if (tid < HID) atomicAdd(&gsum[b*HID + tid], colsum[tid]);
}

// ---------------------------------------------------------------------------
// f_phi
// ---------------------------------------------------------------------------
__global__ void fphi_kernel(const float* __restrict__ gsum,
                            const float* __restrict__ fw1, const float* __restrict__ fb1,
                            const float* __restrict__ fw2, const float* __restrict__ fb2,
                            const float* __restrict__ fw3, const float* __restrict__ fb3,
                            float* __restrict__ out) {
    __shared__ float ga[HID], gb[HID];
    int b = blockIdx.x, tid = threadIdx.x;
    ga[tid] = gsum[b*HID + tid] * (1.0f / (NN*NN));
    __syncthreads();
    float acc = fb1[tid];
    for (int f = 0; f < HID; f++) acc += ga[f] * fw1[f*HID + tid];
    gb[tid] = fmaxf(acc, 0.f);
    __syncthreads();
    acc = fb2[tid];
    for (int f = 0; f < HID; f++) acc += gb[f] * fw2[f*HID + tid];
    ga[tid] = fmaxf(acc, 0.f);
    __syncthreads();
    if (tid < AD) {
        float o = fb3[tid];
        for (int f = 0; f < HID; f++) o += ga[f] * fw3[f*AD + tid];
        out[b*AD + tid] = o;
    }
}

// ---------------------------------------------------------------------------
// Launch
// ---------------------------------------------------------------------------
extern "C" void kernel_launch(void* const* d_in, const int* in_sizes, int n_in,
                              void* d_out, int out_size) {
    (void)in_sizes; (void)n_in; (void)out_size;
    const float* img = (const float*)d_in[0];
    const float* q   = (const float*)d_in[1];
    const float* cw[4] = {(const float*)d_in[2],  (const float*)d_in[6],
                          (const float*)d_in[10], (const float*)d_in[14]};
    const float* cb[4] = {(const float*)d_in[3],  (const float*)d_in[7],
                          (const float*)d_in[11], (const float*)d_in[15]};
    const float* bg[4] = {(const float*)d_in[4],  (const float*)d_in[8],
                          (const float*)d_in[12], (const float*)d_in[16]};
    const float* bb[4] = {(const float*)d_in[5],  (const float*)d_in[9],
                          (const float*)d_in[13], (const float*)d_in[17]};
    const float* gw1 = (const float*)d_in[18]; const float* gb1 = (const float*)d_in[19];
    const float* gw2 = (const float*)d_in[20]; const float* gb2 = (const float*)d_in[21];
    const float* gw3 = (const float*)d_in[22]; const float* gb3 = (const float*)d_in[23];
    const float* gw4 = (const float*)d_in[24]; const float* gb4 = (const float*)d_in[25];
    const float* fw1 = (const float*)d_in[26]; const float* fb1 = (const float*)d_in[27];
    const float* fw2 = (const float*)d_in[28]; const float* fb2 = (const float*)d_in[29];
    const float* fw3 = (const float*)d_in[30]; const float* fb3 = (const float*)d_in[31];
    float* out = (float*)d_out;

    float  *x1, *x2, *x3, *x4, *u, *v, *s, *gsum, *scale, *shift;
    uint32_t* wfp;
    double *bnsum, *bnsq;
    cudaGetSymbolAddress((void**)&x1,    g_x1);
    cudaGetSymbolAddress((void**)&x2,    g_x2);
    cudaGetSymbolAddress((void**)&x3,    g_x3);
    cudaGetSymbolAddress((void**)&x4,    g_x4);
    cudaGetSymbolAddress((void**)&u,     g_u);
    cudaGetSymbolAddress((void**)&v,     g_v);
    cudaGetSymbolAddress((void**)&s,     g_s);
    cudaGetSymbolAddress((void**)&gsum,  g_gsum);
    cudaGetSymbolAddress((void**)&wfp,   g_wf);
    cudaGetSymbolAddress((void**)&scale, g_scale);
    cudaGetSymbolAddress((void**)&shift, g_shift);
    cudaGetSymbolAddress((void**)&bnsum, g_bnsum);
    cudaGetSymbolAddress((void**)&bnsq,  g_bnsq);

    cudaFuncSetAttribute(rn_mma_kernel,
                         cudaFuncAttributeMaxDynamicSharedMemorySize, DYN_RN);

    zero_kernel<<<64, 256>>>(gsum, bnsum, bnsq);
    wfrag_kernel<<<384, 256>>>(gw2, gw3, gw4, wfp);

    conv_relu_kernel<3,24,128,64><<<(BSZ*CH*64*64+255)/256, 256>>>(img, cw[0], cb[0], x1);
    bn_stats_kernel<<<dim3(CH,16), 256>>>(x1, bnsum+0, bnsq+0, 64*64);
    bn_finalize_kernel<<<1, 32>>>(bnsum+0, bnsq+0, bg[0], bb[0], scale, shift, 64*64);
    bn_apply_kernel<<<(BSZ*CH*64*64+255)/256, 256>>>(x1, scale, shift, 64*64, BSZ*CH*64*64);

    conv_relu_kernel<24,24,64,32><<<(BSZ*CH*32*32+255)/256, 256>>>(x1, cw[1], cb[1], x2);
    bn_stats_kernel<<<dim3(CH,8), 256>>>(x2, bnsum+CH, bnsq+CH, 32*32);
    bn_finalize_kernel<<<1, 32>>>(bnsum+CH, bnsq+CH, bg[1], bb[1], scale, shift, 32*32);
    bn_apply_kernel<<<(BSZ*CH*32*32+255)/256, 256>>>(x2, scale, shift, 32*32, BSZ*CH*32*32);

    conv_relu_kernel<24,24,32,16><<<(BSZ*CH*16*16+255)/256, 256>>>(x2, cw[2], cb[2], x3);
    bn_stats_kernel<<<dim3(CH,4), 256>>>(x3, bnsum+2*CH, bnsq+2*CH, 16*16);
    bn_finalize_kernel<<<1, 32>>>(bnsum+2*CH, bnsq+2*CH, bg[2], bb[2], scale, shift, 16*16);
    bn_apply_kernel<<<(BSZ*CH*16*16+255)/256, 256>>>(x3, scale, shift, 16*16, BSZ*CH*16*16);

    conv_relu_kernel<24,24,16,8><<<(BSZ*CH*8*8+255)/256, 256>>>(x3, cw[3], cb[3], x4);
    bn_stats_kernel<<<dim3(CH,2), 256>>>(x4, bnsum+3*CH, bnsq+3*CH, 8*8);
    bn_finalize_kernel<<<1, 32>>>(bnsum+3*CH, bnsq+3*CH, bg[3], bb[3], scale, shift, 8*8);
    bn_apply_kernel<<<(BSZ*CH*8*8+255)/256, 256>>>(x4, scale, shift, 8*8, BSZ*CH*8*8);

    uv_kernel<<<BSZ*NN, 256>>>(x4, gw1, u, v);
    s_kernel<<<BSZ, 256>>>(q, gw1, gb1, s);

    rn_mma_kernel<<<BSZ*NN/2, 512, DYN_RN>>>(u, v, s, gsum, wfp, gb2, gb3, gb4);

    fphi_kernel<<<BSZ, 256>>>(gsum, fw1, fb1, fw2, fb2, fw3, fb3, out);
}

// round 4
// speedup vs baseline: 3.6841x; 1.4846x over previous
#include <cuda_runtime.h>
#include <cuda_fp16.h>
#include <math.h>
#include <stdint.h>

// ---------------------------------------------------------------------------
// Problem constants
// ---------------------------------------------------------------------------
#define BSZ   64
#define IMG   128
#define CH    24
#define QD    11
#define AD    10
#define NN    64      // objects per image (8x8)
#define FD    26      // CH + 2 coords
#define HID   256
#define EPSV  1e-5f

// rn_mma geometry (fp16)
#define M_CTA     128            // pair rows per CTA (2 i-values x 64 j)
#define SA        264            // half-element stride (528B row, 16B aligned)
#define WSLAB_B   32768          // 4 k16-steps of fragment-ordered fp16 weights
#define N_SLABS   12             // 3 layers x 4 slabs
#define DYN_RN    (2*WSLAB_B + M_CTA*SA*2)   // 65536 + 67584 = 133120

// ---------------------------------------------------------------------------
// Scratch
// ---------------------------------------------------------------------------
__device__ float  g_x1[BSZ*CH*64*64];
__device__ float  g_x2[BSZ*CH*32*32];
__device__ float  g_x3[BSZ*CH*16*16];
__device__ float  g_x4[BSZ*CH*8*8];
__device__ float  g_u [BSZ*NN*HID];
__device__ float  g_v [BSZ*NN*HID];
__device__ float  g_s [BSZ*HID];
__device__ float  g_gsum[BSZ*HID];
__device__ uint2  g_wf[3*16*32*32];    // fragment-ordered fp16 weights
__device__ float  g_bnsum[4*CH];
__device__ float  g_bnsq [4*CH];
__device__ float  g_scale[4*CH];
__device__ float  g_shift[4*CH];

// ---------------------------------------------------------------------------
// Helpers
// ---------------------------------------------------------------------------
__device__ __forceinline__ uint32_t smem_u32(const void* p) {
    uint32_t a;
    asm("{ .reg .u64 t; cvta.to.shared.u64 t, %1; cvt.u32.u64 %0, t; }"
        : "=r"(a) : "l"(p));
    return a;
}
__device__ __forceinline__ void mma_f16(float* c, const uint32_t* a,
                                        uint32_t b0, uint32_t b1) {
    asm volatile(
        "mma.sync.aligned.m16n8k16.row.col.f32.f16.f16.f32 "
        "{%0,%1,%2,%3}, {%4,%5,%6,%7}, {%8,%9}, {%0,%1,%2,%3};"
        : "+f"(c[0]), "+f"(c[1]), "+f"(c[2]), "+f"(c[3])
        : "r"(a[0]), "r"(a[1]), "r"(a[2]), "r"(a[3]), "r"(b0), "r"(b1));
}
__device__ __forceinline__ void cp16(uint32_t dst, const void* src) {
    asm volatile("cp.async.cg.shared.global [%0], [%1], 16;"
                 :: "r"(dst), "l"(__cvta_generic_to_global(src)) : "memory");
}
#define CP_COMMIT() asm volatile("cp.async.commit_group;" ::: "memory")
#define CP_WAIT1()  asm volatile("cp.async.wait_group 1;" ::: "memory")
#define CP_WAIT0()  asm volatile("cp.async.wait_group 0;" ::: "memory")

__device__ __forceinline__ uint32_t pack_h2(float lo, float hi) {
    __half2 h = __floats2half2_rn(lo, hi);
    return *(uint32_t*)&h;
}

// ---------------------------------------------------------------------------
__global__ void zero_kernel(float* gsum, float* bnsum, float* bnsq) {
    int idx = blockIdx.x * blockDim.x + threadIdx.x;
    if (idx < BSZ*HID) gsum[idx] = 0.f;
    if (idx < 4*CH) { bnsum[idx] = 0.f; bnsq[idx] = 0.f; }
}

// Fragment-ordered fp16 weights for m16n8k16 (B col-major frag):
// per (layer l, kstep k in 0..15, ngroup jg in 0..31, lane t):
//  n = jg*8 + t/4 ; kk = k*16 + 2*(t%4)
//  b0 = {W[kk][n],  W[kk+1][n]},  b1 = {W[kk+8][n], W[kk+9][n]}
__global__ void wfrag_kernel(const float* __restrict__ gw2,
                             const float* __restrict__ gw3,
                             const float* __restrict__ gw4,
                             uint2* __restrict__ wf) {
    int idx = blockIdx.x * blockDim.x + threadIdx.x;   // [0, 3*16384)
    if (idx >= 3*16384) return;
    int l  = idx >> 14;
    int r  = idx & 16383;
    int k  = r >> 10;
    int jg = (r >> 5) & 31;
    int t  = r & 31;
    const float* g = (l == 0) ? gw2 : (l == 1) ? gw3 : gw4;
    int n  = jg*8 + (t >> 2);
    int kk = k*16 + 2*(t & 3);
    uint2 val;
    val.x = pack_h2(g[(size_t)kk*HID + n],     g[(size_t)(kk+1)*HID + n]);
    val.y = pack_h2(g[(size_t)(kk+8)*HID + n], g[(size_t)(kk+9)*HID + n]);
    wf[idx] = val;
}

// ---------------------------------------------------------------------------
// Fused conv (k=3, s=2, p=1) + optional input-BN + bias + ReLU + channel stats.
// Grid must tile the output exactly; HOUT*HOUT must be a multiple of 32
// (warp-uniform channel for the shfl stats reduction).
// ---------------------------------------------------------------------------
template<int CI, int CO, int HIN, int HOUT, bool APPLY>
__global__ void conv_bn_kernel(const float* __restrict__ in,
                               const float* __restrict__ w,
                               const float* __restrict__ bias,
                               const float* __restrict__ sc_in,
                               const float* __restrict__ sh_in,
                               float* __restrict__ out,
                               float* __restrict__ sum_g,
                               float* __restrict__ sq_g) {
    __shared__ float ws[CI*CO*9];
    __shared__ float bs[CO];
    __shared__ float sci[CI], shi[CI];
    __shared__ float csum[CO], csq[CO];
    for (int i = threadIdx.x; i < CI*CO*9; i += blockDim.x) ws[i] = w[i];
    if (threadIdx.x < CO) {
        bs[threadIdx.x] = bias[threadIdx.x];
        csum[threadIdx.x] = 0.f; csq[threadIdx.x] = 0.f;
    }
    if (APPLY && threadIdx.x < CI) {
        sci[threadIdx.x] = sc_in[threadIdx.x];
        shi[threadIdx.x] = sh_in[threadIdx.x];
    }
    __syncthreads();

    int idx = blockIdx.x * blockDim.x + threadIdx.x;
    int ox = idx % HOUT;
    int oy = (idx / HOUT) % HOUT;
    int co = (idx / (HOUT*HOUT)) % CO;
    int b  = idx / (HOUT*HOUT*CO);

    float acc = bs[co];
    int iy0 = oy*2 - 1, ix0 = ox*2 - 1;
    #pragma unroll
    for (int ci = 0; ci < CI; ci++) {
        const float* ip = in + ((size_t)(b*CI + ci) * HIN) * HIN;
        const float* wp = ws + (co*CI + ci) * 9;
        float sc = APPLY ? sci[ci] : 1.f;
        float sh = APPLY ? shi[ci] : 0.f;
        #pragma unroll
        for (int ky = 0; ky < 3; ky++) {
            int iy = iy0 + ky;
            if (iy < 0 || iy >= HIN) continue;
            #pragma unroll
            for (int kx = 0; kx < 3; kx++) {
                int ix = ix0 + kx;
                if (ix < 0 || ix >= HIN) continue;
                float raw = ip[iy*HIN + ix];
                float x = APPLY ? (raw*sc + sh) : raw;
                acc += x * wp[ky*3 + kx];
            }
        }
    }
    float val = fmaxf(acc, 0.f);
    out[idx] = val;

    // warp-uniform channel stats
    float s = val, s2 = val*val;
    #pragma unroll
    for (int off = 16; off > 0; off >>= 1) {
        s  += __shfl_xor_sync(0xFFFFFFFFu, s,  off);
        s2 += __shfl_xor_sync(0xFFFFFFFFu, s2, off);
    }
    if ((threadIdx.x & 31) == 0) {
        atomicAdd(&csum[co], s);
        atomicAdd(&csq [co], s2);
    }
    __syncthreads();
    if (threadIdx.x < CO) {
        if (csum[threadIdx.x] != 0.f) atomicAdd(&sum_g[threadIdx.x], csum[threadIdx.x]);
        if (csq [threadIdx.x] != 0.f) atomicAdd(&sq_g [threadIdx.x], csq [threadIdx.x]);
    }
}

__global__ void bn_finalize_kernel(const float* __restrict__ sum,
                                   const float* __restrict__ sq,
                                   const float* __restrict__ bg,
                                   const float* __restrict__ bb,
                                   float* __restrict__ scale,
                                   float* __restrict__ shift,
                                   int HW) {
    int c = threadIdx.x;
    if (c >= CH) return;
    float cnt = (float)(BSZ * HW);
    float m   = sum[c] / cnt;
    float var = sq[c] / cnt - m * m;
    float inv = rsqrtf(var + EPSV);
    float sc  = bg[c] * inv;
    scale[c] = sc;
    shift[c] = bb[c] - m * sc;
}

// ---------------------------------------------------------------------------
// Layer-1 factorization (BN4 applied inline)
// ---------------------------------------------------------------------------
__global__ void uv_kernel(const float* __restrict__ x4,
                          const float* __restrict__ sc4,
                          const float* __restrict__ sh4,
                          const float* __restrict__ gw1,
                          float* __restrict__ u, float* __restrict__ v) {
    __shared__ float o[FD];
    int bn = blockIdx.x;
    int b = bn >> 6, n = bn & 63;
    int tid = threadIdx.x;
    if (tid < CH)       o[tid] = x4[(b*CH + tid)*64 + n] * sc4[tid] + sh4[tid];
    else if (tid == CH)     o[CH]   = (float)(n >> 3) * 0.125f;
    else if (tid == CH + 1) o[CH+1] = (float)(n & 7)  * 0.125f;
    __syncthreads();
    float us = 0.f, vs = 0.f;
    #pragma unroll
    for (int f = 0; f < FD; f++) {
        float ov = o[f];
        us += ov * gw1[f*HID + tid];
        vs += ov * gw1[(FD + f)*HID + tid];
    }
    u[bn*HID + tid] = us;
    v[bn*HID + tid] = vs;
}

__global__ void s_kernel(const float* __restrict__ q,
                         const float* __restrict__ gw1,
                         const float* __restrict__ gb1,
                         float* __restrict__ s) {
    __shared__ float qv[QD];
    int b = blockIdx.x, tid = threadIdx.x;
    if (tid < QD) qv[tid] = q[b*QD + tid];
    __syncthreads();
    float acc = gb1[tid];
    #pragma unroll
    for (int t = 0; t < QD; t++)
        acc += qv[t] * gw1[(2*FD + t)*HID + tid];
    s[b*HID + tid] = acc;
}

// ---------------------------------------------------------------------------
// Tensor-core relational core (mma.sync fp16, fp32 accumulate).
// CTA: 512 thr (16 warps = 4 Mgroups x 4 Ngroups), M=128 rows, N=256, K=256, x3.
// hA: in-place SMEM fp16 activations, stride 264 halves.
// Weights: fragment-ordered fp16, cp.async double-buffered 4-kstep slabs.
// ---------------------------------------------------------------------------
__global__ void __launch_bounds__(512, 1)
rn_mma_kernel(const float* __restrict__ u, const float* __restrict__ v,
              const float* __restrict__ sb, float* __restrict__ gsum,
              const uint2* __restrict__ wf,
              const float* __restrict__ gb2, const float* __restrict__ gb3,
              const float* __restrict__ gb4) {
    extern __shared__ char dyn[];
    __half* hAh = (__half*)(dyn + 2*WSLAB_B);
    const uint2* wbuf2 = (const uint2*)dyn;
    const uint32_t wsm = smem_u32(dyn);
    __shared__ float biasS[3*HID];
    __shared__ float colsum[HID];

    const int tid  = threadIdx.x;
    const int lane = tid & 31;
    const int warp = tid >> 5;
    const int mg   = warp & 3;    // row group: rows [mg*32, mg*32+32)
    const int ng   = warp >> 2;   // col group: cols [ng*64, ng*64+64)
    const int tig  = lane & 3;    // thread-in-group

    for (int i = tid; i < HID; i += 512) {
        biasS[i]         = gb2[i];
        biasS[HID + i]   = gb3[i];
        biasS[2*HID + i] = gb4[i];
    }
    if (tid < HID) colsum[tid] = 0.f;

    // ---- build h1 (fp16) in hA ----
    const int b  = blockIdx.x >> 5;
    const int i0 = (blockIdx.x & 31) * 2;
    {
        const int row = tid >> 2;
        const int c0  = (tid & 3) * 64;
        const int ii  = i0 + (row >> 6);
        const int jj  = row & 63;
        const float* up = u  + (size_t)(b*NN + ii) * HID;
        const float* vp = v  + (size_t)(b*NN + jj) * HID;
        const float* sp = sb + (size_t)b * HID;
        #pragma unroll
        for (int f = 0; f < 8; f++) {
            int c = c0 + f*8;
            float4 u0 = *(const float4*)(up + c);
            float4 v0 = *(const float4*)(vp + c);
            float4 s0 = *(const float4*)(sp + c);
            float4 u1 = *(const float4*)(up + c + 4);
            float4 v1 = *(const float4*)(vp + c + 4);
            float4 s1 = *(const float4*)(sp + c + 4);
            uint4 hq;
            hq.x = pack_h2(fmaxf(u0.x+v0.x+s0.x, 0.f), fmaxf(u0.y+v0.y+s0.y, 0.f));
            hq.y = pack_h2(fmaxf(u0.z+v0.z+s0.z, 0.f), fmaxf(u0.w+v0.w+s0.w, 0.f));
            hq.z = pack_h2(fmaxf(u1.x+v1.x+s1.x, 0.f), fmaxf(u1.y+v1.y+s1.y, 0.f));
            hq.w = pack_h2(fmaxf(u1.z+v1.z+s1.z, 0.f), fmaxf(u1.w+v1.w+s1.w, 0.f));
            *(uint4*)(hAh + row*SA + c) = hq;
        }
    }

    // ---- prefetch W slab 0 ----
    {
        const char* src = (const char*)wf;
        #pragma unroll
        for (int i = 0; i < 4; i++)
            cp16(wsm + (i*512 + tid)*16, src + (i*512 + tid)*16);
        CP_COMMIT();
    }

    float acc[2][8][4];

    #pragma unroll 1
    for (int sl = 0; sl < N_SLABS; sl++) {
        const int l   = sl >> 2;
        const int cur = sl & 1;
        __syncthreads();                       // prev compute done; h1/epilogue visible
        if (sl + 1 < N_SLABS) {
            const char* src = (const char*)wf + (size_t)(sl + 1) * WSLAB_B;
            uint32_t dst = wsm + (cur ^ 1) * WSLAB_B;
            #pragma unroll
            for (int i = 0; i < 4; i++)
                cp16(dst + (i*512 + tid)*16, src + (i*512 + tid)*16);
            CP_COMMIT();
            CP_WAIT1();
        } else {
            CP_WAIT0();
        }
        __syncthreads();                       // slab sl visible to all

        if ((sl & 3) == 0) {
            #pragma unroll
            for (int mt = 0; mt < 2; mt++)
                #pragma unroll
                for (int j = 0; j < 8; j++)
                    #pragma unroll
                    for (int c = 0; c < 4; c++)
                        acc[mt][j][c] = 0.f;
        }

        // compute 4 k16-steps of this slab
        const uint2* wslab = wbuf2 + cur * (WSLAB_B/8);
        const int kbase = (sl & 3) * 4;
        #pragma unroll
        for (int kk = 0; kk < 4; kk++) {
            const int kcol = (kbase + kk) * 16;          // halves
            uint32_t a[2][4];
            #pragma unroll
            for (int mt = 0; mt < 2; mt++) {
                int rA = mg*32 + mt*16 + (lane >> 2);
                const __half* base = hAh + rA*SA + kcol + 2*tig;
                a[mt][0] = *(const uint32_t*)(base);
                a[mt][1] = *(const uint32_t*)(base + 8*SA);
                a[mt][2] = *(const uint32_t*)(base + 8);
                a[mt][3] = *(const uint32_t*)(base + 8*SA + 8);
            }
            #pragma unroll
            for (int j = 0; j < 8; j++) {
                uint2 bb = wslab[(kk*32 + (ng*8 + j))*32 + lane];
                mma_f16(acc[0][j], a[0], bb.x, bb.y);
                mma_f16(acc[1][j], a[1], bb.x, bb.y);
            }
        }

        if ((sl & 3) == 3) {
            __syncthreads();                   // all K-loops done before hA overwrite
            if (l < 2) {
                const float* bl = biasS + l*HID;
                #pragma unroll
                for (int mt = 0; mt < 2; mt++) {
                    int rA = mg*32 + mt*16 + (lane >> 2);
                    #pragma unroll
                    for (int j = 0; j < 8; j++) {
                        int col = ng*64 + j*8 + 2*tig;
                        float b0 = bl[col], b1 = bl[col+1];
                        uint32_t lo = pack_h2(fmaxf(acc[mt][j][0] + b0, 0.f),
                                              fmaxf(acc[mt][j][1] + b1, 0.f));
                        uint32_t hi = pack_h2(fmaxf(acc[mt][j][2] + b0, 0.f),
                                              fmaxf(acc[mt][j][3] + b1, 0.f));
                        *(uint32_t*)(hAh + rA*SA + col)       = lo;
                        *(uint32_t*)(hAh + (rA+8)*SA + col)   = hi;
                    }
                }
                __syncthreads();
            } else {
                // final layer: relu(acc+bias), reduce over rows, SMEM colsum
                const float* bl = biasS + 2*HID;
                #pragma unroll
                for (int j = 0; j < 8; j++) {
                    int col = ng*64 + j*8 + 2*tig;
                    float b0 = bl[col], b1 = bl[col+1];
                    float s0 = 0.f, s1 = 0.f;
                    #pragma unroll
                    for (int mt = 0; mt < 2; mt++) {
                        s0 += fmaxf(acc[mt][j][0] + b0, 0.f)
                            + fmaxf(acc[mt][j][2] + b0, 0.f);
                        s1 += fmaxf(acc[mt][j][1] + b1, 0.f)
                            + fmaxf(acc[mt][j][3] + b1, 0.f);
                    }
                    #pragma unroll
                    for (int off = 4; off < 32; off <<= 1) {
                        s0 += __shfl_xor_sync(0xFFFFFFFFu, s0, off);
                        s1 += __shfl_xor_sync(0xFFFFFFFFu, s1, off);
                    }
                    if (lane < 4) {
                        atomicAdd(&colsum[col],     s0);
                        atomicAdd(&colsum[col + 1], s1);
                    }
                }
            }
        }
    }

    __syncthreads();
    if (tid < HID) atomicAdd(&gsum[b*HID + tid], colsum[tid]);
}

// ---------------------------------------------------------------------------
// f_phi
// ---------------------------------------------------------------------------
__global__ void fphi_kernel(const float* __restrict__ gsum,
                            const float* __restrict__ fw1, const float* __restrict__ fb1,
                            const float* __restrict__ fw2, const float* __restrict__ fb2,
                            const float* __restrict__ fw3, const float* __restrict__ fb3,
                            float* __restrict__ out) {
    __shared__ float ga[HID], gb[HID];
    int b = blockIdx.x, tid = threadIdx.x;
    ga[tid] = gsum[b*HID + tid] * (1.0f / (NN*NN));
    __syncthreads();
    float acc = fb1[tid];
    for (int f = 0; f < HID; f++) acc += ga[f] * fw1[f*HID + tid];
    gb[tid] = fmaxf(acc, 0.f);
    __syncthreads();
    acc = fb2[tid];
    for (int f = 0; f < HID; f++) acc += gb[f] * fw2[f*HID + tid];
    ga[tid] = fmaxf(acc, 0.f);
    __syncthreads();
    if (tid < AD) {
        float o = fb3[tid];
        for (int f = 0; f < HID; f++) o += ga[f] * fw3[f*AD + tid];
        out[b*AD + tid] = o;
    }
}

// ---------------------------------------------------------------------------
// Launch
// ---------------------------------------------------------------------------
extern "C" void kernel_launch(void* const* d_in, const int* in_sizes, int n_in,
                              void* d_out, int out_size) {
    (void)in_sizes; (void)n_in; (void)out_size;
    const float* img = (const float*)d_in[0];
    const float* q   = (const float*)d_in[1];
    const float* cw[4] = {(const float*)d_in[2],  (const float*)d_in[6],
                          (const float*)d_in[10], (const float*)d_in[14]};
    const float* cb[4] = {(const float*)d_in[3],  (const float*)d_in[7],
                          (const float*)d_in[11], (const float*)d_in[15]};
    const float* bg[4] = {(const float*)d_in[4],  (const float*)d_in[8],
                          (const float*)d_in[12], (const float*)d_in[16]};
    const float* bb[4] = {(const float*)d_in[5],  (const float*)d_in[9],
                          (const float*)d_in[13], (const float*)d_in[17]};
    const float* gw1 = (const float*)d_in[18]; const float* gb1 = (const float*)d_in[19];
    const float* gw2 = (const float*)d_in[20]; const float* gb2 = (const float*)d_in[21];
    const float* gw3 = (const float*)d_in[22]; const float* gb3 = (const float*)d_in[23];
    const float* gw4 = (const float*)d_in[24]; const float* gb4 = (const float*)d_in[25];
    const float* fw1 = (const float*)d_in[26]; const float* fb1 = (const float*)d_in[27];
    const float* fw2 = (const float*)d_in[28]; const float* fb2 = (const float*)d_in[29];
    const float* fw3 = (const float*)d_in[30]; const float* fb3 = (const float*)d_in[31];
    float* out = (float*)d_out;

    float *x1, *x2, *x3, *x4, *u, *v, *s, *gsum, *scale, *shift, *bnsum, *bnsq;
    uint2* wfp;
    cudaGetSymbolAddress((void**)&x1,    g_x1);
    cudaGetSymbolAddress((void**)&x2,    g_x2);
    cudaGetSymbolAddress((void**)&x3,    g_x3);
    cudaGetSymbolAddress((void**)&x4,    g_x4);
    cudaGetSymbolAddress((void**)&u,     g_u);
    cudaGetSymbolAddress((void**)&v,     g_v);
    cudaGetSymbolAddress((void**)&s,     g_s);
    cudaGetSymbolAddress((void**)&gsum,  g_gsum);
    cudaGetSymbolAddress((void**)&wfp,   g_wf);
    cudaGetSymbolAddress((void**)&scale, g_scale);
    cudaGetSymbolAddress((void**)&shift, g_shift);
    cudaGetSymbolAddress((void**)&bnsum, g_bnsum);
    cudaGetSymbolAddress((void**)&bnsq,  g_bnsq);

    cudaFuncSetAttribute(rn_mma_kernel,
                         cudaFuncAttributeMaxDynamicSharedMemorySize, DYN_RN);

    zero_kernel<<<64, 256>>>(gsum, bnsum, bnsq);
    wfrag_kernel<<<192, 256>>>(gw2, gw3, gw4, wfp);

    // conv block 1 (no input BN)
    conv_bn_kernel<3,24,128,64,false><<<BSZ*CH*64*64/256, 256>>>(
        img, cw[0], cb[0], nullptr, nullptr, x1, bnsum+0, bnsq+0);
    bn_finalize_kernel<<<1, 32>>>(bnsum+0, bnsq+0, bg[0], bb[0],
                                  scale+0, shift+0, 64*64);
    // conv block 2 (applies BN1 to input)
    conv_bn_kernel<24,24,64,32,true><<<BSZ*CH*32*32/256, 256>>>(
        x1, cw[1], cb[1], scale+0, shift+0, x2, bnsum+CH, bnsq+CH);
    bn_finalize_kernel<<<1, 32>>>(bnsum+CH, bnsq+CH, bg[1], bb[1],
                                  scale+CH, shift+CH, 32*32);
    // conv block 3
    conv_bn_kernel<24,24,32,16,true><<<BSZ*CH*16*16/256, 256>>>(
        x2, cw[2], cb[2], scale+CH, shift+CH, x3, bnsum+2*CH, bnsq+2*CH);
    bn_finalize_kernel<<<1, 32>>>(bnsum+2*CH, bnsq+2*CH, bg[2], bb[2],
                                  scale+2*CH, shift+2*CH, 16*16);
    // conv block 4
    conv_bn_kernel<24,24,16,8,true><<<BSZ*CH*8*8/256, 256>>>(
        x3, cw[3], cb[3], scale+2*CH, shift+2*CH, x4, bnsum+3*CH, bnsq+3*CH);
    bn_finalize_kernel<<<1, 32>>>(bnsum+3*CH, bnsq+3*CH, bg[3], bb[3],
                                  scale+3*CH, shift+3*CH, 8*8);

    // g_theta layer-1 factorization (BN4 applied inline)
    uv_kernel<<<BSZ*NN, 256>>>(x4, scale+3*CH, shift+3*CH, gw1, u, v);
    s_kernel<<<BSZ, 256>>>(q, gw1, gb1, s);

    // fp16 tensor-core relational core
    rn_mma_kernel<<<BSZ*NN/2, 512, DYN_RN>>>(u, v, s, gsum, wfp, gb2, gb3, gb4);

    fphi_kernel<<<BSZ, 256>>>(gsum, fw1, fb1, fw2, fb2, fw3, fb3, out);
}